// round 4
// baseline (speedup 1.0000x reference)
#include <cuda_runtime.h>
#include <cuda_bf16.h>
#include <cstdint>
#include <cstddef>

// ---------------------------------------------------------------------------
// QuantizedLinear: out[8192,16384] = x[8192,4096] @ (Wint*scale)^T + bias
// Baseline-sm_103 build (no 'a' features): legacy mma.sync IMMA path.
// x -> per-row 15-bit quant split into two int8 planes (hi,lo); W -> int8.
// out = rs[m]*scale[n]*(128*C_hi + C_lo) + bias[n], C_* exact int32 GEMMs.
// ---------------------------------------------------------------------------

#define MTOT 8192
#define NTOT 16384
#define KTOT 4096
#define KT   (KTOT / 64)        // 64 k-chunks of 64
#define NBUF 4                  // ring buffers; lookahead 2

// Stage layout: Ahi[128x64 pad80] Alo[...] B[128x64 pad80]
#define ROWPAD 80
#define AHI_OFF 0
#define ALO_OFF 10240
#define B_OFF   20480
#define STAGE_BYTES 30720
#define SMEM_BYTES (NBUF * STAGE_BYTES)   // 122880

// Scratch (device globals: no allocations allowed)
static __device__ __align__(16) signed char g_xhi[(size_t)MTOT * KTOT];
static __device__ __align__(16) signed char g_xlo[(size_t)MTOT * KTOT];
static __device__ __align__(16) signed char g_w8 [(size_t)NTOT * KTOT];
static __device__ float g_rs[MTOT];

// ---------------- helpers ----------------
__device__ __forceinline__ uint32_t smem_u32(const void* p) {
    uint32_t a;
    asm("{ .reg .u64 t; cvta.to.shared.u64 t, %1; cvt.u32.u64 %0, t; }" : "=r"(a) : "l"(p));
    return a;
}
__device__ __forceinline__ void cpasync16(uint32_t dst, const void* src) {
    asm volatile("cp.async.cg.shared.global [%0], [%1], 16;" :: "r"(dst), "l"(src));
}
#define CP_COMMIT() asm volatile("cp.async.commit_group;" ::: "memory")
#define CP_WAIT(N)  asm volatile("cp.async.wait_group %0;" :: "n"(N) : "memory")

#define LDSM4(R, ADDR) \
    asm volatile("ldmatrix.sync.aligned.m8n8.x4.shared.b16 {%0,%1,%2,%3}, [%4];" \
        : "=r"((R)[0]), "=r"((R)[1]), "=r"((R)[2]), "=r"((R)[3]) : "r"(ADDR))

#define MMA_S8(C, A, B0, B1) \
    asm volatile("mma.sync.aligned.m16n8k32.row.col.s32.s8.s8.s32 " \
        "{%0,%1,%2,%3}, {%4,%5,%6,%7}, {%8,%9}, {%0,%1,%2,%3};" \
        : "+r"((C)[0]), "+r"((C)[1]), "+r"((C)[2]), "+r"((C)[3]) \
        : "r"((A)[0]), "r"((A)[1]), "r"((A)[2]), "r"((A)[3]), "r"(B0), "r"(B1))

__device__ __forceinline__ uint32_t pack4(int b0, int b1, int b2, int b3) {
    return (uint32_t)(uint8_t)(signed char)b0 |
           ((uint32_t)(uint8_t)(signed char)b1 << 8) |
           ((uint32_t)(uint8_t)(signed char)b2 << 16) |
           ((uint32_t)(uint8_t)(signed char)b3 << 24);
}

// ---------------- Prepass: x -> per-row 15-bit (hi,lo) int8 ----------------
// One block per row (8192 blocks x 256 threads). Row = 1024 float4.
__global__ void __launch_bounds__(256) quant_x_kernel(const float4* __restrict__ x) {
    __shared__ float red[8];
    __shared__ float s_inv;
    const int m = blockIdx.x;
    const int t = threadIdx.x;
    const float4* row = x + (size_t)m * (KTOT / 4);

    float4 v[4];
    float mx = 0.f;
#pragma unroll
    for (int j = 0; j < 4; ++j) {
        v[j] = row[t + 256 * j];
        mx = fmaxf(mx, fmaxf(fmaxf(fabsf(v[j].x), fabsf(v[j].y)),
                             fmaxf(fabsf(v[j].z), fabsf(v[j].w))));
    }
#pragma unroll
    for (int o = 16; o > 0; o >>= 1) mx = fmaxf(mx, __shfl_xor_sync(0xffffffffu, mx, o));
    if ((t & 31) == 0) red[t >> 5] = mx;
    __syncthreads();
    if (t == 0) {
        float m2 = red[0];
#pragma unroll
        for (int w = 1; w < 8; ++w) m2 = fmaxf(m2, red[w]);
        s_inv = (m2 > 0.f) ? (16256.f / m2) : 0.f;
        g_rs[m] = m2 * (1.f / 16256.f);
    }
    __syncthreads();
    const float inv = s_inv;

    uint32_t* ohi = reinterpret_cast<uint32_t*>(g_xhi + (size_t)m * KTOT);
    uint32_t* olo = reinterpret_cast<uint32_t*>(g_xlo + (size_t)m * KTOT);
#pragma unroll
    for (int j = 0; j < 4; ++j) {
        const float f[4] = {v[j].x, v[j].y, v[j].z, v[j].w};
        int hi[4], lo[4];
#pragma unroll
        for (int e = 0; e < 4; ++e) {
            int iv = __float2int_rn(f[e] * inv);          // |iv| <= 16256
            hi[e] = (iv + 64) >> 7;                        // in [-127,127]
            lo[e] = iv - (hi[e] << 7);                     // in [-64,63]
        }
        ohi[t + 256 * j] = pack4(hi[0], hi[1], hi[2], hi[3]);
        olo[t + 256 * j] = pack4(lo[0], lo[1], lo[2], lo[3]);
    }
}

// ---------------- Prepass: W int32 -> int8 (exact) ----------------
__global__ void __launch_bounds__(256) quant_w_kernel(const int4* __restrict__ w) {
    const size_t g = (size_t)blockIdx.x * 256 + threadIdx.x;   // handles 16 ints
    int4 a = w[g * 4 + 0], b = w[g * 4 + 1], c = w[g * 4 + 2], d = w[g * 4 + 3];
    uint4 o;
    o.x = pack4(a.x, a.y, a.z, a.w);
    o.y = pack4(b.x, b.y, b.z, b.w);
    o.z = pack4(c.x, c.y, c.z, c.w);
    o.w = pack4(d.x, d.y, d.z, d.w);
    reinterpret_cast<uint4*>(g_w8)[g] = o;
}

// ---------------- Main GEMM ----------------
// CTA 128x128, 256 threads, warp grid 4(M) x 2(N); warp tile 32x64.
// Two int32 accumulators (hi,lo). 4-buffer / lookahead-2 cp.async pipeline,
// single __syncthreads per k-iteration (hazard distances verified).
__global__ void __launch_bounds__(256, 1) qlin_imma(
    float* __restrict__ out, const float* __restrict__ scale, const float* __restrict__ bias)
{
    extern __shared__ char smem[];
    const uint32_t sb = smem_u32(smem);
    const int tid  = threadIdx.x;
    const int wid  = tid >> 5;
    const int lane = tid & 31;
    const int warpM = wid & 3;          // 4 x 32 rows
    const int warpN = wid >> 2;         // 2 x 64 cols

    // L2-friendly raster: bands of 8 tm x 128 tn
    const int band = blockIdx.x >> 10;
    const int w    = blockIdx.x & 1023;
    const int tm   = band * 8 + (w & 7);      // 0..63
    const int tn   = w >> 3;                  // 0..127

    // ---- cp.async geometry: thread -> (row, 2 chunks of 16B) ----
    const int ldrow = tid >> 1;               // 0..127
    const int ldc   = (tid & 1) * 2;          // chunk 0 or 2
    const uint32_t dA = (uint32_t)ldrow * ROWPAD + (uint32_t)ldc * 16;
    const signed char* pAhi = g_xhi + (size_t)(tm * 128 + ldrow) * KTOT + ldc * 16;
    const signed char* pAlo = g_xlo + (size_t)(tm * 128 + ldrow) * KTOT + ldc * 16;
    const signed char* pB   = g_w8  + (size_t)(tn * 128 + ldrow) * KTOT + ldc * 16;

#define LOAD_STAGE(J) do { \
        const uint32_t st_ = sb + ((J) & 3) * STAGE_BYTES; \
        const int ko_ = (J) * 64; \
        cpasync16(st_ + AHI_OFF + dA,      pAhi + ko_); \
        cpasync16(st_ + AHI_OFF + dA + 16, pAhi + ko_ + 16); \
        cpasync16(st_ + ALO_OFF + dA,      pAlo + ko_); \
        cpasync16(st_ + ALO_OFF + dA + 16, pAlo + ko_ + 16); \
        cpasync16(st_ + B_OFF   + dA,      pB + ko_); \
        cpasync16(st_ + B_OFF   + dA + 16, pB + ko_ + 16); \
        CP_COMMIT(); \
    } while (0)

    // ---- ldmatrix per-lane offsets ----
    // A: lanes 0-15 rows 0-15 @k0-15, lanes 16-31 rows 0-15 @k16-31
    const uint32_t aoffs = (uint32_t)(warpM * 32 + (lane & 15)) * ROWPAD
                         + (uint32_t)((lane >> 4) * 16);
    // B: lanes 0-7 n0-7@k0, 8-15 n0-7@k16, 16-23 n8-15@k0, 24-31 n8-15@k16
    const uint32_t boffs = B_OFF
                         + (uint32_t)(warpN * 64 + (lane & 7) + ((lane >> 4) << 3)) * ROWPAD
                         + (uint32_t)(((lane >> 3) & 1) * 16);

    int acch[2][8][4];
    int accl[2][8][4];
#pragma unroll
    for (int im = 0; im < 2; ++im)
#pragma unroll
        for (int jn = 0; jn < 8; ++jn)
#pragma unroll
            for (int r = 0; r < 4; ++r) { acch[im][jn][r] = 0; accl[im][jn][r] = 0; }

    // Prologue: stages 0,1 in flight
    LOAD_STAGE(0);
    LOAD_STAGE(1);

#pragma unroll 1
    for (int i = 0; i < KT; ++i) {
        // Load stage i+2 into buffer (i+2)&3. That buffer was read in compute(i-2),
        // which every warp completed before the single barrier of iteration i-1.
        if (i + 2 < KT) { LOAD_STAGE(i + 2); } else { CP_COMMIT(); }
        CP_WAIT(2);                   // stage i resident (this thread's view)
        __syncthreads();              // all threads' portions visible

        const uint32_t stg = sb + (i & 3) * STAGE_BYTES;
#pragma unroll
        for (int kk = 0; kk < 2; ++kk) {
            uint32_t ah[2][4], al[2][4], bf[4][4];
            LDSM4(ah[0], stg + aoffs + kk * 32);
            LDSM4(ah[1], stg + aoffs + 16 * ROWPAD + kk * 32);
            LDSM4(al[0], stg + ALO_OFF + aoffs + kk * 32);
            LDSM4(al[1], stg + ALO_OFF + aoffs + 16 * ROWPAD + kk * 32);
#pragma unroll
            for (int j2 = 0; j2 < 4; ++j2)
                LDSM4(bf[j2], stg + boffs + (uint32_t)(j2 * 16 * ROWPAD) + kk * 32);
#pragma unroll
            for (int im = 0; im < 2; ++im)
#pragma unroll
                for (int j2 = 0; j2 < 4; ++j2) {
                    MMA_S8(acch[im][2 * j2],     ah[im], bf[j2][0], bf[j2][1]);
                    MMA_S8(acch[im][2 * j2 + 1], ah[im], bf[j2][2], bf[j2][3]);
                    MMA_S8(accl[im][2 * j2],     al[im], bf[j2][0], bf[j2][1]);
                    MMA_S8(accl[im][2 * j2 + 1], al[im], bf[j2][2], bf[j2][3]);
                }
        }
    }
#undef LOAD_STAGE

    // ---- epilogue: out = rs[m]*scale[n]*(128*hi+lo) + bias[n] ----
    const int mrow = tm * 128 + warpM * 32 + (lane >> 2);
    const int ncol = tn * 128 + warpN * 64 + (lane & 3) * 2;
#pragma unroll
    for (int im = 0; im < 2; ++im) {
        const int r0 = mrow + im * 16;
        const int r1 = r0 + 8;
        const float rs0 = g_rs[r0];
        const float rs1 = g_rs[r1];
        float* o0 = out + (size_t)r0 * NTOT;
        float* o1 = out + (size_t)r1 * NTOT;
#pragma unroll
        for (int jn = 0; jn < 8; ++jn) {
            const int c = ncol + jn * 8;
            const float s0 = __ldg(scale + c),     s1 = __ldg(scale + c + 1);
            const float b0 = __ldg(bias + c),      b1 = __ldg(bias + c + 1);
            float2 v0, v1;
            v0.x = fmaf(rs0 * s0, fmaf(128.f, (float)acch[im][jn][0], (float)accl[im][jn][0]), b0);
            v0.y = fmaf(rs0 * s1, fmaf(128.f, (float)acch[im][jn][1], (float)accl[im][jn][1]), b1);
            v1.x = fmaf(rs1 * s0, fmaf(128.f, (float)acch[im][jn][2], (float)accl[im][jn][2]), b0);
            v1.y = fmaf(rs1 * s1, fmaf(128.f, (float)acch[im][jn][3], (float)accl[im][jn][3]), b1);
            *reinterpret_cast<float2*>(o0 + c) = v0;
            *reinterpret_cast<float2*>(o1 + c) = v1;
        }
    }
}

// ---------------- Launch ----------------
extern "C" void kernel_launch(void* const* d_in, const int* in_sizes, int n_in,
                              void* d_out, int out_size) {
    (void)in_sizes; (void)n_in; (void)out_size;
    const float* x     = (const float*)d_in[0];   // [4,2048,4096] fp32
    const int*   wint  = (const int*)d_in[1];     // [16384,4096] int32
    const float* scale = (const float*)d_in[2];   // [16384,1] fp32
    const float* bias  = (const float*)d_in[3];   // [16384] fp32
    float* out = (float*)d_out;                   // [4,2048,16384] fp32

    quant_x_kernel<<<MTOT, 256>>>((const float4*)x);
    quant_w_kernel<<<(int)((size_t)NTOT * KTOT / 16 / 256), 256>>>((const int4*)wint);

    cudaFuncSetAttribute(qlin_imma, cudaFuncAttributeMaxDynamicSharedMemorySize, SMEM_BYTES);
    qlin_imma<<<(MTOT / 128) * (NTOT / 128), 256, SMEM_BYTES>>>(out, scale, bias);
}